// round 13
// baseline (speedup 1.0000x reference)
#include <cuda_runtime.h>
#include <cstdint>

#define NR      116
#define NT      192            // threads per block (6 warps)
#define NW      6              // warps per block
#define GRID    152            // one CTA per SM (GB300 = 152 SMs)
#define NTOT    (16*3*512*512) // 12,582,912
#define NV4     (NTOT/4)       // 3,145,728
#define ST      5              // cp.async pipeline stages

// Shared layout (dynamic):
//   float2 hist[NR*NT]  (sum, count-as-f32)   178,176 B  (conflict-free: bank=f(tid))
//   stages[ST]: {R float4[NT]; F float4[NT]; M int4[NT]}  5 x 9,216 B
#define HIST_BYTES  (NR * NT * 8)
#define STG_ARR     (NT * 16)                 // 3072 B per array per stage
#define STG_STRIDE  (3 * STG_ARR)             // 9216 B per stage
#define SMEM_TOTAL  (HIST_BYTES + ST * STG_STRIDE)   // 224,256 B

// Per-block partial (sum, count) per region + last-block ticket.
__device__ float2   g_part[GRID * NR];
__device__ unsigned g_ticket = 0;

__device__ __forceinline__ uint32_t smem_u32(const void* p)
{
    return (uint32_t)__cvta_generic_to_shared(p);
}

// Issue one stage's 3 x 16B cp.async into this thread's private slot, then
// close the group (empty group when invalid keeps group counting uniform).
__device__ __forceinline__ void stage_fill(uint32_t slot,
                                           const float4* Rp, const float4* Fp,
                                           const int4* Mp, int p, bool valid)
{
    if (valid) {
        asm volatile(
            "cp.async.cg.shared.global [%0], [%1], 16;\n\t"
            "cp.async.cg.shared.global [%2], [%3], 16;\n\t"
            "cp.async.cg.shared.global [%4], [%5], 16;\n"
            :: "r"(slot),               "l"(Rp + p),
               "r"(slot + STG_ARR),     "l"(Fp + p),
               "r"(slot + 2 * STG_ARR), "l"(Mp + p)
            : "memory");
    }
    asm volatile("cp.async.commit_group;" ::: "memory");
}

// Accumulate one scalar: single LDS.64 + 2 FADD + STS.64 (fused sum & count).
__device__ __forceinline__ void acc1(float2* slot0, float x, float y, int r)
{
    float2* p = slot0 + r * NT;
    float2 v = *p;
    v.x += fabsf(x - y);
    v.y += 1.0f;
    *p = v;
}

__device__ __forceinline__ void acc4(float2* slot0, float4 a, float4 b, int4 m)
{
    acc1(slot0, a.x, b.x, m.x);
    acc1(slot0, a.y, b.y, m.y);
    acc1(slot0, a.z, b.z, m.z);
    acc1(slot0, a.w, b.w, m.w);
}

__global__ void __launch_bounds__(NT, 1)
fused_kernel(const float* __restrict__ realp,
             const float* __restrict__ fakep,
             const int*   __restrict__ rmapp,
             float* __restrict__ out)
{
    extern __shared__ unsigned char smem_raw[];
    float2*        hist = (float2*)smem_raw;
    unsigned char* stg  = smem_raw + HIST_BYTES;

    const int tid  = threadIdx.x;
    const int warp = tid >> 5;
    const int lane = tid & 31;

    // Zero hist (vectorized, conflict-free).
    {
        float4* h4 = (float4*)smem_raw;
        const int n4 = HIST_BYTES / 16;
        for (int k = tid; k < n4; k += NT)
            h4[k] = make_float4(0.f, 0.f, 0.f, 0.f);
    }
    __syncthreads();

    float2* slot0 = hist + tid;              // this thread's column

    const float4* __restrict__ R = (const float4*)realp;
    const float4* __restrict__ F = (const float4*)fakep;
    const int4*   __restrict__ M = (const int4*)rmapp;

    const int T = GRID * NT;
    const int p0 = blockIdx.x * NT + tid;
    const uint32_t aslot0 = smem_u32(stg) + tid * 16;

    // Prologue: fill ST stages (one commit group each).
    #pragma unroll
    for (int s = 0; s < ST; s++)
        stage_fill(aslot0 + s * STG_STRIDE, R, F, M, p0 + s * T,
                   (p0 + s * T) < NV4);

    int pin = p0 + ST * T;     // next vec4 index to fetch
    int s   = 0;

    // Main loop: thread-private stages, no block barriers. wait_group ST-1
    // guarantees the oldest group (stage s) has landed; refill it, then
    // accumulate.
    #pragma unroll 1
    for (int pc = p0; pc < NV4; pc += T) {
        asm volatile("cp.async.wait_group %0;" :: "n"(ST - 1) : "memory");

        const unsigned char* sb = stg + s * STG_STRIDE + tid * 16;
        float4 a = *(const float4*)(sb);
        float4 b = *(const float4*)(sb + STG_ARR);
        int4   m = *(const int4*)(sb + 2 * STG_ARR);

        stage_fill(aslot0 + s * STG_STRIDE, R, F, M, pin, pin < NV4);
        pin += T;

        acc4(slot0, a, b, m);
        if (++s == ST) s = 0;
    }
    asm volatile("cp.async.wait_all;" ::: "memory");

    __syncthreads();

    // Block reduction: warp w handles regions w, w+6, ... Lanes stride the
    // thread axis (conflict-free), then shfl-combine.
    for (int r = warp; r < NR; r += NW) {
        float sv = 0.f, cv = 0.f;
        #pragma unroll
        for (int k = 0; k < NT / 32; k++) {
            float2 v = hist[r * NT + lane + k * 32];
            sv += v.x;
            cv += v.y;
        }
        #pragma unroll
        for (int o = 16; o; o >>= 1) {
            sv += __shfl_xor_sync(0xffffffffu, sv, o);
            cv += __shfl_xor_sync(0xffffffffu, cv, o);
        }
        if (lane == 0)
            g_part[blockIdx.x * NR + r] = make_float2(sv, cv);
    }

    // ---- last-block finalize (threadfence-reduction pattern) ----
    __threadfence();
    __syncthreads();

    __shared__ unsigned is_last;
    if (tid == 0)
        is_last = (atomicAdd(&g_ticket, 1u) == GRID - 1) ? 1u : 0u;
    __syncthreads();
    if (!is_last)
        return;
    __threadfence();

    // Reuse hist smem for the 116-region final reduction.
    float* sh_s = (float*)smem_raw;
    float* sh_m = sh_s + NR;
    __shared__ float sh_max;

    if (tid < NR) {
        float sv = 0.f, cvf = 0.f;
        #pragma unroll 8
        for (int b = 0; b < GRID; b++) {
            float2 v = g_part[b * NR + tid];
            sv  += v.x;
            cvf += v.y;
        }
        sh_s[tid] = sv;
        sh_m[tid] = sv / (cvf + 1e-6f);
    }
    __syncthreads();

    if (tid < 32) {
        float mx = 0.f;   // running max starts at 0 (matches max(0, max_r m_r))
        for (int r = tid; r < NR; r += 32)
            mx = fmaxf(mx, sh_m[r]);
        #pragma unroll
        for (int o = 16; o; o >>= 1)
            mx = fmaxf(mx, __shfl_xor_sync(0xffffffffu, mx, o));
        if (tid == 0) sh_max = mx;
    }
    __syncthreads();

    if (tid < 32) {
        const float inv = 1e-3f / (sh_max + 1e-6f);
        float tot = 0.f;
        for (int r = tid; r < NR; r += 32)
            tot += sh_s[r] * (1.0f + inv * sh_m[r]);
        #pragma unroll
        for (int o = 16; o; o >>= 1)
            tot += __shfl_xor_sync(0xffffffffu, tot, o);
        if (tid == 0) {
            out[0] = tot / (float)NTOT;
            g_ticket = 0;       // reset for deterministic replay
        }
    }
}

extern "C" void kernel_launch(void* const* d_in, const int* in_sizes, int n_in,
                              void* d_out, int out_size)
{
    const float* realp = (const float*)d_in[0];
    const float* fakep = (const float*)d_in[1];
    const int*   rmapp = (const int*)d_in[2];

    cudaFuncSetAttribute(fused_kernel,
                         cudaFuncAttributeMaxDynamicSharedMemorySize,
                         SMEM_TOTAL);

    fused_kernel<<<GRID, NT, SMEM_TOTAL>>>(realp, fakep, rmapp, (float*)d_out);
}

// round 14
// speedup vs baseline: 1.0499x; 1.0499x over previous
#include <cuda_runtime.h>
#include <cstdint>

#define NR      116
#define NT      320            // threads per block (10 warps)
#define NW      10             // warps per block
#define GRID    152            // one CTA per SM (GB300 = 152 SMs)
#define NTOT    (16*3*512*512) // 12,582,912
#define NV4     (NTOT/4)       // 3,145,728
#define ST      5              // cp.async pipeline stages
#define FSCALE  4096.0f        // fixed-point scale 2^12 for |diff|
#define FINV    (1.0f/4096.0f)

// Shared layout (dynamic):
//   u32 hist[NR*NT]  packed {count[31:24], sum_fixed[23:0]}   148,480 B
//       (bank = tid mod 32 -> conflict-free for any region pattern)
//   stages[ST]: {R float4[NT]; F float4[NT]; M int4[NT]}      5 x 15,360 B
#define HIST_BYTES  (NR * NT * 4)
#define STG_ARR     (NT * 16)                 // 5120 B per array per stage
#define STG_STRIDE  (3 * STG_ARR)             // 15360 B per stage
#define SMEM_TOTAL  (HIST_BYTES + ST * STG_STRIDE)   // 225,280 B

// Per-block partial (sum, count) per region + last-block ticket.
__device__ float2   g_part[GRID * NR];
__device__ unsigned g_ticket = 0;

__device__ __forceinline__ uint32_t smem_u32(const void* p)
{
    return (uint32_t)__cvta_generic_to_shared(p);
}

// Issue one stage's 3 x 16B cp.async into this thread's private slot, then
// close the group (empty group when invalid keeps group counting uniform).
__device__ __forceinline__ void stage_fill(uint32_t slot,
                                           const float4* Rp, const float4* Fp,
                                           const int4* Mp, int p, bool valid)
{
    if (valid) {
        asm volatile(
            "cp.async.cg.shared.global [%0], [%1], 16;\n\t"
            "cp.async.cg.shared.global [%2], [%3], 16;\n\t"
            "cp.async.cg.shared.global [%4], [%5], 16;\n"
            :: "r"(slot),               "l"(Rp + p),
               "r"(slot + STG_ARR),     "l"(Fp + p),
               "r"(slot + 2 * STG_ARR), "l"(Mp + p)
            : "memory");
    }
    asm volatile("cp.async.commit_group;" ::: "memory");
}

// Accumulate one scalar: fixed-point |x-y| and +1 count packed in one u32
// -> single LDS.32 + IADD3 + STS.32 on the histogram.
__device__ __forceinline__ void acc1(uint32_t* slot0, float x, float y, int r)
{
    float d = fabsf(x - y) * FSCALE;
    uint32_t q = (uint32_t)__float2int_rn(d) + (1u << 24);
    slot0[r * NT] += q;
}

__device__ __forceinline__ void acc4(uint32_t* slot0, float4 a, float4 b, int4 m)
{
    acc1(slot0, a.x, b.x, m.x);
    acc1(slot0, a.y, b.y, m.y);
    acc1(slot0, a.z, b.z, m.z);
    acc1(slot0, a.w, b.w, m.w);
}

__global__ void __launch_bounds__(NT, 1)
fused_kernel(const float* __restrict__ realp,
             const float* __restrict__ fakep,
             const int*   __restrict__ rmapp,
             float* __restrict__ out)
{
    extern __shared__ unsigned char smem_raw[];
    uint32_t*      hist = (uint32_t*)smem_raw;
    unsigned char* stg  = smem_raw + HIST_BYTES;

    const int tid  = threadIdx.x;
    const int warp = tid >> 5;
    const int lane = tid & 31;

    // Zero hist (vectorized, conflict-free).
    {
        uint4* h4 = (uint4*)smem_raw;
        const int n4 = HIST_BYTES / 16;
        for (int k = tid; k < n4; k += NT)
            h4[k] = make_uint4(0u, 0u, 0u, 0u);
    }
    __syncthreads();

    uint32_t* slot0 = hist + tid;            // this thread's column

    const float4* __restrict__ R = (const float4*)realp;
    const float4* __restrict__ F = (const float4*)fakep;
    const int4*   __restrict__ M = (const int4*)rmapp;

    const int T = GRID * NT;
    const int p0 = blockIdx.x * NT + tid;
    const uint32_t aslot0 = smem_u32(stg) + tid * 16;

    // Prologue: fill ST stages (one commit group each).
    #pragma unroll
    for (int s = 0; s < ST; s++)
        stage_fill(aslot0 + s * STG_STRIDE, R, F, M, p0 + s * T,
                   (p0 + s * T) < NV4);

    int pin = p0 + ST * T;     // next vec4 index to fetch
    int s   = 0;

    // Main loop: thread-private stages, no block barriers. wait_group ST-1
    // guarantees the oldest group (stage s) has landed; refill it, then
    // accumulate.
    #pragma unroll 1
    for (int pc = p0; pc < NV4; pc += T) {
        asm volatile("cp.async.wait_group %0;" :: "n"(ST - 1) : "memory");

        const unsigned char* sb = stg + s * STG_STRIDE + tid * 16;
        float4 a = *(const float4*)(sb);
        float4 b = *(const float4*)(sb + STG_ARR);
        int4   m = *(const int4*)(sb + 2 * STG_ARR);

        stage_fill(aslot0 + s * STG_STRIDE, R, F, M, pin, pin < NV4);
        pin += T;

        acc4(slot0, a, b, m);
        if (++s == ST) s = 0;
    }
    asm volatile("cp.async.wait_all;" ::: "memory");

    __syncthreads();

    // Block reduction: warp w handles regions w, w+10, ... Integer unpack:
    // sum_fixed in low 24 bits, count in high 8. Per-block region totals fit
    // u32 comfortably (<= ~800 elems * 32768 < 2^25). Lanes stride the thread
    // axis (bank = lane -> conflict-free), then shfl-combine.
    for (int r = warp; r < NR; r += NW) {
        uint32_t usum = 0, ucnt = 0;
        #pragma unroll
        for (int k = 0; k < NT / 32; k++) {
            uint32_t v = hist[r * NT + lane + k * 32];
            usum += v & 0x00FFFFFFu;
            ucnt += v >> 24;
        }
        #pragma unroll
        for (int o = 16; o; o >>= 1) {
            usum += __shfl_xor_sync(0xffffffffu, usum, o);
            ucnt += __shfl_xor_sync(0xffffffffu, ucnt, o);
        }
        if (lane == 0)
            g_part[blockIdx.x * NR + r] =
                make_float2((float)usum * FINV, (float)ucnt);
    }

    // ---- last-block finalize (threadfence-reduction pattern) ----
    __threadfence();
    __syncthreads();

    __shared__ unsigned is_last;
    if (tid == 0)
        is_last = (atomicAdd(&g_ticket, 1u) == GRID - 1) ? 1u : 0u;
    __syncthreads();
    if (!is_last)
        return;
    __threadfence();

    // Reuse hist smem for the 116-region final reduction.
    float* sh_s = (float*)smem_raw;
    float* sh_m = sh_s + NR;
    __shared__ float sh_max;

    if (tid < NR) {
        float sv = 0.f, cvf = 0.f;
        #pragma unroll 8
        for (int b = 0; b < GRID; b++) {
            float2 v = g_part[b * NR + tid];
            sv  += v.x;
            cvf += v.y;
        }
        sh_s[tid] = sv;
        sh_m[tid] = sv / (cvf + 1e-6f);
    }
    __syncthreads();

    if (tid < 32) {
        float mx = 0.f;   // running max starts at 0 (matches max(0, max_r m_r))
        for (int r = tid; r < NR; r += 32)
            mx = fmaxf(mx, sh_m[r]);
        #pragma unroll
        for (int o = 16; o; o >>= 1)
            mx = fmaxf(mx, __shfl_xor_sync(0xffffffffu, mx, o));
        if (tid == 0) sh_max = mx;
    }
    __syncthreads();

    if (tid < 32) {
        const float inv = 1e-3f / (sh_max + 1e-6f);
        float tot = 0.f;
        for (int r = tid; r < NR; r += 32)
            tot += sh_s[r] * (1.0f + inv * sh_m[r]);
        #pragma unroll
        for (int o = 16; o; o >>= 1)
            tot += __shfl_xor_sync(0xffffffffu, tot, o);
        if (tid == 0) {
            out[0] = tot / (float)NTOT;
            g_ticket = 0;       // reset for deterministic replay
        }
    }
}

extern "C" void kernel_launch(void* const* d_in, const int* in_sizes, int n_in,
                              void* d_out, int out_size)
{
    const float* realp = (const float*)d_in[0];
    const float* fakep = (const float*)d_in[1];
    const int*   rmapp = (const int*)d_in[2];

    cudaFuncSetAttribute(fused_kernel,
                         cudaFuncAttributeMaxDynamicSharedMemorySize,
                         SMEM_TOTAL);

    fused_kernel<<<GRID, NT, SMEM_TOTAL>>>(realp, fakep, rmapp, (float*)d_out);
}

// round 16
// speedup vs baseline: 1.0671x; 1.0164x over previous
#include <cuda_runtime.h>
#include <cstdint>

#define NR      116
#define NT      320            // threads per block (10 warps)
#define NW      10             // warps per block
#define GRID    152            // one CTA per SM (GB300 = 152 SMs)
#define NTOT    (16*3*512*512) // 12,582,912
#define NV4     (NTOT/4)       // 3,145,728
#define ST      5              // cp.async pipeline stages
#define FSCALE  4096.0f        // fixed-point scale 2^12 for |diff|
#define FINV    (1.0f/4096.0f)
#define ROWB    (NT * 4)       // hist row stride in bytes (1280)

// Shared layout (dynamic):
//   u32 hist[NR*NT]  packed {count[31:24], sum_fixed[23:0]}   148,480 B
//       (bank = tid mod 32 -> conflict-free for any region pattern)
//   stages[ST]: {R float4[NT]; F float4[NT]; M int4[NT]}      5 x 15,360 B
#define HIST_BYTES  (NR * NT * 4)
#define STG_ARR     (NT * 16)                 // 5120 B per array per stage
#define STG_STRIDE  (3 * STG_ARR)             // 15360 B per stage
#define SMEM_TOTAL  (HIST_BYTES + ST * STG_STRIDE)   // 225,280 B

// Per-block partial (sum, count) per region + last-block ticket.
__device__ float2   g_part[GRID * NR];
__device__ unsigned g_ticket = 0;

__device__ __forceinline__ uint32_t smem_u32(const void* p)
{
    return (uint32_t)__cvta_generic_to_shared(p);
}

// Issue one stage's 3 x 16B cp.async into this thread's private slot, then
// close the group (empty group when invalid keeps group counting uniform).
__device__ __forceinline__ void stage_fill(uint32_t slot,
                                           const float4* Rp, const float4* Fp,
                                           const int4* Mp, int p, bool valid)
{
    if (valid) {
        asm volatile(
            "cp.async.cg.shared.global [%0], [%1], 16;\n\t"
            "cp.async.cg.shared.global [%2], [%3], 16;\n\t"
            "cp.async.cg.shared.global [%4], [%5], 16;\n"
            :: "r"(slot),               "l"(Rp + p),
               "r"(slot + STG_ARR),     "l"(Fp + p),
               "r"(slot + 2 * STG_ARR), "l"(Mp + p)
            : "memory");
    }
    asm volatile("cp.async.commit_group;" ::: "memory");
}

// Packed fixed-point contribution: count in [31:24], |x-y|*4096 in [23:0].
__device__ __forceinline__ uint32_t qval(float x, float y)
{
    return (uint32_t)__float2int_rn(fabsf(x - y) * FSCALE) + (1u << 24);
}

// Batched 4-slot RMW. Caller guarantees live slots have distinct addresses,
// so issuing all loads before all stores is safe. Inline asm forces the
// batched order (ptxas would otherwise serialize ld/st pairs because it
// cannot prove the dynamic addresses don't alias). Chain: one LDS latency
// per 4 elements instead of four.
__device__ __forceinline__ void rmw4(uint32_t a0, uint32_t a1, uint32_t a2,
                                     uint32_t a3,
                                     uint32_t q0, uint32_t q1, uint32_t q2,
                                     uint32_t q3,
                                     uint32_t al0, uint32_t al1, uint32_t al2)
{
    asm volatile(
        "{\n\t"
        ".reg .pred p0, p1, p2;\n\t"
        ".reg .u32 t0, t1, t2, t3;\n\t"
        "setp.ne.u32 p0, %4, 0;\n\t"
        "setp.ne.u32 p1, %5, 0;\n\t"
        "setp.ne.u32 p2, %6, 0;\n\t"
        "@p0 ld.shared.u32 t0, [%0];\n\t"
        "@p1 ld.shared.u32 t1, [%1];\n\t"
        "@p2 ld.shared.u32 t2, [%2];\n\t"
        "ld.shared.u32 t3, [%3];\n\t"
        "add.u32 t0, t0, %7;\n\t"
        "add.u32 t1, t1, %8;\n\t"
        "add.u32 t2, t2, %9;\n\t"
        "add.u32 t3, t3, %10;\n\t"
        "@p0 st.shared.u32 [%0], t0;\n\t"
        "@p1 st.shared.u32 [%1], t1;\n\t"
        "@p2 st.shared.u32 [%2], t2;\n\t"
        "st.shared.u32 [%3], t3;\n\t"
        "}"
        :: "r"(a0), "r"(a1), "r"(a2), "r"(a3),
           "r"(al0), "r"(al1), "r"(al2),
           "r"(q0), "r"(q1), "r"(q2), "r"(q3)
        : "memory");
}

// Accumulate one vec4: dedup equal regions (merge into the LAST occurrence,
// branch-free), then one batched RMW with distinct live addresses.
__device__ __forceinline__ void acc4(uint32_t abase, float4 a, float4 b, int4 m)
{
    uint32_t q0 = qval(a.x, b.x);
    uint32_t q1 = qval(a.y, b.y);
    uint32_t q2 = qval(a.z, b.z);
    uint32_t q3 = qval(a.w, b.w);

    uint32_t al0 = 1u, al1 = 1u, al2 = 1u;
    if (m.y == m.x)        { q1 += q0; al0 = 0u; }
    if (m.z == m.x && al0) { q2 += q0; al0 = 0u; }
    if (m.z == m.y)        { q2 += q1; al1 = 0u; }
    if (m.w == m.x && al0) { q3 += q0; al0 = 0u; }
    if (m.w == m.y && al1) { q3 += q1; al1 = 0u; }
    if (m.w == m.z)        { q3 += q2; al2 = 0u; }

    rmw4(abase + (uint32_t)m.x * ROWB, abase + (uint32_t)m.y * ROWB,
         abase + (uint32_t)m.z * ROWB, abase + (uint32_t)m.w * ROWB,
         q0, q1, q2, q3, al0, al1, al2);
}

__global__ void __launch_bounds__(NT, 1)
fused_kernel(const float* __restrict__ realp,
             const float* __restrict__ fakep,
             const int*   __restrict__ rmapp,
             float* __restrict__ out)
{
    extern __shared__ unsigned char smem_raw[];
    uint32_t*      hist = (uint32_t*)smem_raw;
    unsigned char* stg  = smem_raw + HIST_BYTES;

    const int tid  = threadIdx.x;
    const int warp = tid >> 5;
    const int lane = tid & 31;

    // Zero hist (vectorized, conflict-free).
    {
        uint4* h4 = (uint4*)smem_raw;
        const int n4 = HIST_BYTES / 16;
        for (int k = tid; k < n4; k += NT)
            h4[k] = make_uint4(0u, 0u, 0u, 0u);
    }
    __syncthreads();

    const uint32_t abase = smem_u32(hist) + (uint32_t)tid * 4u;

    const float4* __restrict__ R = (const float4*)realp;
    const float4* __restrict__ F = (const float4*)fakep;
    const int4*   __restrict__ M = (const int4*)rmapp;

    const int T = GRID * NT;
    const int p0 = blockIdx.x * NT + tid;
    const uint32_t aslot0 = smem_u32(stg) + tid * 16;

    // Prologue: fill ST stages (one commit group each).
    #pragma unroll
    for (int s = 0; s < ST; s++)
        stage_fill(aslot0 + s * STG_STRIDE, R, F, M, p0 + s * T,
                   (p0 + s * T) < NV4);

    int pin = p0 + ST * T;     // next vec4 index to fetch
    int s   = 0;

    // Main loop: thread-private stages, no block barriers. wait_group ST-1
    // guarantees the oldest group (stage s) has landed; refill it, then
    // accumulate 4 elements with ONE batched RMW.
    #pragma unroll 1
    for (int pc = p0; pc < NV4; pc += T) {
        asm volatile("cp.async.wait_group %0;" :: "n"(ST - 1) : "memory");

        const unsigned char* sb = stg + s * STG_STRIDE + tid * 16;
        float4 a = *(const float4*)(sb);
        float4 b = *(const float4*)(sb + STG_ARR);
        int4   m = *(const int4*)(sb + 2 * STG_ARR);

        stage_fill(aslot0 + s * STG_STRIDE, R, F, M, pin, pin < NV4);
        pin += T;

        acc4(abase, a, b, m);
        if (++s == ST) s = 0;
    }
    asm volatile("cp.async.wait_all;" ::: "memory");

    __syncthreads();

    // Block reduction: warp w handles regions w, w+10, ... Integer unpack:
    // sum_fixed in low 24 bits, count in high 8. Lanes stride the thread
    // axis (bank = lane -> conflict-free), then shfl-combine.
    for (int r = warp; r < NR; r += NW) {
        uint32_t usum = 0, ucnt = 0;
        #pragma unroll
        for (int k = 0; k < NT / 32; k++) {
            uint32_t v = hist[r * NT + lane + k * 32];
            usum += v & 0x00FFFFFFu;
            ucnt += v >> 24;
        }
        #pragma unroll
        for (int o = 16; o; o >>= 1) {
            usum += __shfl_xor_sync(0xffffffffu, usum, o);
            ucnt += __shfl_xor_sync(0xffffffffu, ucnt, o);
        }
        if (lane == 0)
            g_part[blockIdx.x * NR + r] =
                make_float2((float)usum * FINV, (float)ucnt);
    }

    // ---- last-block finalize (threadfence-reduction pattern) ----
    __threadfence();
    __syncthreads();

    __shared__ unsigned is_last;
    if (tid == 0)
        is_last = (atomicAdd(&g_ticket, 1u) == GRID - 1) ? 1u : 0u;
    __syncthreads();
    if (!is_last)
        return;
    __threadfence();

    // Reuse hist smem for the 116-region final reduction.
    float* sh_s = (float*)smem_raw;
    float* sh_m = sh_s + NR;
    __shared__ float sh_max;

    if (tid < NR) {
        float sv = 0.f, cvf = 0.f;
        #pragma unroll 8
        for (int b = 0; b < GRID; b++) {
            float2 v = g_part[b * NR + tid];
            sv  += v.x;
            cvf += v.y;
        }
        sh_s[tid] = sv;
        sh_m[tid] = sv / (cvf + 1e-6f);
    }
    __syncthreads();

    if (tid < 32) {
        float mx = 0.f;   // running max starts at 0 (matches max(0, max_r m_r))
        for (int r = tid; r < NR; r += 32)
            mx = fmaxf(mx, sh_m[r]);
        #pragma unroll
        for (int o = 16; o; o >>= 1)
            mx = fmaxf(mx, __shfl_xor_sync(0xffffffffu, mx, o));
        if (tid == 0) sh_max = mx;
    }
    __syncthreads();

    if (tid < 32) {
        const float inv = 1e-3f / (sh_max + 1e-6f);
        float tot = 0.f;
        for (int r = tid; r < NR; r += 32)
            tot += sh_s[r] * (1.0f + inv * sh_m[r]);
        #pragma unroll
        for (int o = 16; o; o >>= 1)
            tot += __shfl_xor_sync(0xffffffffu, tot, o);
        if (tid == 0) {
            out[0] = tot / (float)NTOT;
            g_ticket = 0;       // reset for deterministic replay
        }
    }
}

extern "C" void kernel_launch(void* const* d_in, const int* in_sizes, int n_in,
                              void* d_out, int out_size)
{
    const float* realp = (const float*)d_in[0];
    const float* fakep = (const float*)d_in[1];
    const int*   rmapp = (const int*)d_in[2];

    cudaFuncSetAttribute(fused_kernel,
                         cudaFuncAttributeMaxDynamicSharedMemorySize,
                         SMEM_TOTAL);

    fused_kernel<<<GRID, NT, SMEM_TOTAL>>>(realp, fakep, rmapp, (float*)d_out);
}